// round 1
// baseline (speedup 1.0000x reference)
#include <cuda_runtime.h>
#include <cstddef>

// Problem constants
#define M_BATCH 8192
#define D_DIM   512
#define H_DIM   2048
#define N_STEPS 10
#define DT      0.1f

// Scratch (device globals — no allocation allowed in kernel_launch)
__device__ float g_y [M_BATCH * D_DIM];   // current state y
__device__ float g_yt[M_BATCH * D_DIM];   // y + dt*k1
__device__ float g_k1[M_BATCH * D_DIM];   // k1
__device__ float g_h [M_BATCH * H_DIM];   // tanh hidden activations

// Tiling
constexpr int BM = 128, BN = 128, BK = 16, TM = 8, TN = 8;
// 256 threads: 16x16 thread grid, each computes TMxTN

// MODE 0: C = tanh(A@B + bias)                         (GEMM1)
// MODE 1: k1 = A@B + bias; C=k1; C2 = yin + DT*k1      (GEMM2, k1 pass)
// MODE 2: k2 = A@B + bias; C = yin + 0.5*DT*(k1in+k2)  (GEMM2, k2 pass)
template<int MODE>
__global__ void __launch_bounds__(256, 2)
gemm_fused(const float* __restrict__ A, const float* __restrict__ B,
           const float* __restrict__ bias,
           float* __restrict__ C, float* __restrict__ C2,
           const float* __restrict__ yin, const float* __restrict__ k1in,
           int M, int N, int K)
{
    __shared__ float As[BK][BM + 4];   // A tile, transposed to [k][m], padded
    __shared__ float Bs[BK][BN];       // B tile [k][n]

    const int tid = threadIdx.x;
    const int tr  = tid >> 4;          // 0..15
    const int tc  = tid & 15;          // 0..15
    const int bm  = blockIdx.y * BM;
    const int bn  = blockIdx.x * BN;

    float acc[TM][TN];
    #pragma unroll
    for (int i = 0; i < TM; i++)
        #pragma unroll
        for (int j = 0; j < TN; j++)
            acc[i][j] = 0.0f;

    for (int k0 = 0; k0 < K; k0 += BK) {
        // ---- Load A tile: BM rows x BK cols (row-major, stride K) ----
        // 128*16/4 = 512 float4 loads, 2 per thread
        #pragma unroll
        for (int ld = tid; ld < (BM * BK) / 4; ld += 256) {
            int row = ld >> 2;         // BK/4 = 4 float4 per row
            int kc4 = ld & 3;
            const float4 v = *reinterpret_cast<const float4*>(
                A + (size_t)(bm + row) * K + k0 + kc4 * 4);
            As[kc4 * 4 + 0][row] = v.x;
            As[kc4 * 4 + 1][row] = v.y;
            As[kc4 * 4 + 2][row] = v.z;
            As[kc4 * 4 + 3][row] = v.w;
        }
        // ---- Load B tile: BK rows x BN cols (row-major, stride N) ----
        #pragma unroll
        for (int ld = tid; ld < (BK * BN) / 4; ld += 256) {
            int row = ld >> 5;         // BN/4 = 32 float4 per row
            int c4  = ld & 31;
            *reinterpret_cast<float4*>(&Bs[row][c4 * 4]) =
                *reinterpret_cast<const float4*>(
                    B + (size_t)(k0 + row) * N + bn + c4 * 4);
        }
        __syncthreads();

        // ---- Compute ----
        #pragma unroll
        for (int k = 0; k < BK; k++) {
            float a[TM], b[TN];
            #pragma unroll
            for (int i = 0; i < TM; i++) a[i] = As[k][tr * TM + i];
            #pragma unroll
            for (int j = 0; j < TN; j++) b[j] = Bs[k][tc * TN + j];
            #pragma unroll
            for (int i = 0; i < TM; i++)
                #pragma unroll
                for (int j = 0; j < TN; j++)
                    acc[i][j] = fmaf(a[i], b[j], acc[i][j]);
        }
        __syncthreads();
    }

    // ---- Fused epilogue ----
    #pragma unroll
    for (int i = 0; i < TM; i++) {
        const int row = bm + tr * TM + i;
        #pragma unroll
        for (int j = 0; j < TN; j++) {
            const int col = bn + tc * TN + j;
            const size_t idx = (size_t)row * N + col;
            const float v = acc[i][j] + bias[col];
            if (MODE == 0) {
                C[idx] = tanhf(v);
            } else if (MODE == 1) {
                C[idx]  = v;                       // k1
                C2[idx] = yin[idx] + DT * v;       // yt = y + dt*k1
            } else {
                C[idx] = yin[idx] + (0.5f * DT) * (k1in[idx] + v);  // y_next
            }
        }
    }
}

extern "C" void kernel_launch(void* const* d_in, const int* in_sizes, int n_in,
                              void* d_out, int out_size)
{
    const float* y0 = (const float*)d_in[0];
    const float* W1 = (const float*)d_in[1];
    const float* b1 = (const float*)d_in[2];
    const float* W2 = (const float*)d_in[3];
    const float* b2 = (const float*)d_in[4];
    float* out = (float*)d_out;

    float *py, *pyt, *pk1, *ph;
    cudaGetSymbolAddress((void**)&py,  g_y);
    cudaGetSymbolAddress((void**)&pyt, g_yt);
    cudaGetSymbolAddress((void**)&pk1, g_k1);
    cudaGetSymbolAddress((void**)&ph,  g_h);

    const dim3 blk(256);
    const dim3 grid1(H_DIM / BN, M_BATCH / BM);  // 16 x 64  (GEMM1: out 8192x2048)
    const dim3 grid2(D_DIM / BN, M_BATCH / BM);  //  4 x 64  (GEMM2: out 8192x512)

    const float* ycur = y0;  // step 0 reads y0 directly; later steps read g_y
    for (int s = 0; s < N_STEPS; s++) {
        // k1 pass: h = tanh(y@W1+b1); k1 = h@W2+b2; yt = y + dt*k1
        gemm_fused<0><<<grid1, blk>>>(ycur, W1, b1, ph, nullptr, nullptr, nullptr,
                                      M_BATCH, H_DIM, D_DIM);
        gemm_fused<1><<<grid2, blk>>>(ph, W2, b2, pk1, pyt, ycur, nullptr,
                                      M_BATCH, D_DIM, H_DIM);
        // k2 pass: h = tanh(yt@W1+b1); k2 = h@W2+b2; y = y + 0.05*(k1+k2)
        gemm_fused<0><<<grid1, blk>>>(pyt, W1, b1, ph, nullptr, nullptr, nullptr,
                                      M_BATCH, H_DIM, D_DIM);
        float* yo = (s == N_STEPS - 1) ? out : py;
        gemm_fused<2><<<grid2, blk>>>(ph, W2, b2, yo, nullptr, ycur, pk1,
                                      M_BATCH, D_DIM, H_DIM);
        ycur = py;
    }
}

// round 3
// speedup vs baseline: 3.0526x; 3.0526x over previous
#include <cuda_runtime.h>
#include <cstdint>
#include <cstddef>

#define M_BATCH 8192
#define D_DIM   512
#define H_DIM   2048
#define N_STEPS 10

// ---------------- scratch (device globals; no allocation allowed) ----------
__device__ float g_y [M_BATCH * D_DIM];            // fp32 state
__device__ float g_yr[M_BATCH * D_DIM];            // tf32-rounded copy of state
__device__ float g_yt[M_BATCH * D_DIM];            // rounded y + dt*k1
__device__ float g_k1[M_BATCH * D_DIM];            // fp32 k1
__device__ float g_h [M_BATCH * H_DIM];            // rounded tanh hidden
__device__ float g_W1t[(size_t)H_DIM * D_DIM];     // W1^T rounded, [N=H, K=D]
__device__ float g_W2t[(size_t)D_DIM * H_DIM];     // W2^T rounded, [N=D, K=H]

// ---------------- helpers ----------------------------------------------------
__device__ __forceinline__ uint32_t smem_u32(const void* p) {
    uint32_t a;
    asm("{ .reg .u64 t; cvta.to.shared.u64 t, %1; cvt.u32.u64 %0, t; }" : "=r"(a) : "l"(p));
    return a;
}
__device__ __forceinline__ float rtf32(float x) {           // round-to-nearest tf32
    uint32_t u;
    asm("cvt.rna.tf32.f32 %0, %1;" : "=r"(u) : "f"(x));
    return __uint_as_float(u);
}
__device__ __forceinline__ void mma_tf32(float c[4], const uint32_t a[4], const uint32_t b[2]) {
    asm volatile(
        "mma.sync.aligned.m16n8k8.row.col.f32.tf32.tf32.f32 "
        "{%0,%1,%2,%3}, {%4,%5,%6,%7}, {%8,%9}, {%0,%1,%2,%3};"
        : "+f"(c[0]), "+f"(c[1]), "+f"(c[2]), "+f"(c[3])
        : "r"(a[0]), "r"(a[1]), "r"(a[2]), "r"(a[3]), "r"(b[0]), "r"(b[1]));
}
#define CP_ASYNC16(dst, src) \
    asm volatile("cp.async.cg.shared.global [%0], [%1], 16;" :: "r"(dst), "l"(src))
#define CP_COMMIT() asm volatile("cp.async.commit_group;" ::: "memory")
#define CP_WAIT(n)  asm volatile("cp.async.wait_group %0;" :: "n"(n) : "memory")

// ---------------- GEMM config ------------------------------------------------
// CTA tile 128x128, BK=32, 4 smem stages, 256 threads (8 warps: 2 m x 4 n, 64x32 each)
constexpr int ROWF  = 36;                 // padded floats per row (144 B, 16B aligned)
constexpr int AS    = 128 * ROWF;         // floats per A (or B) stage
constexpr int STG   = 2 * AS;             // floats per stage (A + B)
constexpr int NSTG  = 4;
constexpr int SMEM_TOTAL = NSTG * STG * 4;  // 147456 B

// MODE 0: C = rtf32(tanh(acc + bias))
// MODE 1: C = acc + bias (k1, fp32);  C2 = rtf32(yin + 0.1*k1)   (yt)
// MODE 2: yn = yin + 0.05*(k1in + (acc+bias)); C = yn (fp32); C2 = rtf32(yn)
template<int MODE>
__global__ void __launch_bounds__(256)
gemm_mma(const float* __restrict__ A,     // [M, K] row-major
         const float* __restrict__ Bw,    // [N, K] row-major (K-major weights)
         const float* __restrict__ bias,
         float* __restrict__ C, float* __restrict__ C2,
         const float* __restrict__ yin, const float* __restrict__ k1in,
         int N, int K)
{
    extern __shared__ float sm[];
    const int tid  = threadIdx.x;
    const int lane = tid & 31;
    const int wid  = tid >> 5;
    const int wm   = (wid & 1) * 64;      // warp m offset in CTA tile
    const int wn   = (wid >> 1) * 32;     // warp n offset
    const int g    = lane >> 2;           // 0..7
    const int tig  = lane & 3;            // 0..3
    const int bm   = blockIdx.y * 128;
    const int bn   = blockIdx.x * 128;
    const int ktiles = K / 32;

    float acc[4][4][4];
    #pragma unroll
    for (int i = 0; i < 4; i++)
        #pragma unroll
        for (int j = 0; j < 4; j++)
            #pragma unroll
            for (int e = 0; e < 4; e++)
                acc[i][j][e] = 0.0f;

    // ---- async tile loader: 128 rows x 32 floats per operand ----
    auto load_tile = [&](int kt) {
        const int s = kt & (NSTG - 1);
        float* sa = sm + s * STG;
        float* sb = sa + AS;
        #pragma unroll
        for (int i = 0; i < 4; i++) {
            const int t   = tid + i * 256;       // 0..1023
            const int row = t >> 3;
            const int ch  = t & 7;
            const uint32_t da = smem_u32(sa + row * ROWF + ch * 4);
            CP_ASYNC16(da, A  + (size_t)(bm + row) * K + kt * 32 + ch * 4);
            const uint32_t db = smem_u32(sb + row * ROWF + ch * 4);
            CP_ASYNC16(db, Bw + (size_t)(bn + row) * K + kt * 32 + ch * 4);
        }
    };

    // ---- prologue: 3 stages in flight ----
    #pragma unroll
    for (int kt = 0; kt < NSTG - 1; kt++) {
        if (kt < ktiles) load_tile(kt);
        CP_COMMIT();
    }

    // ---- mainloop ----
    for (int kt = 0; kt < ktiles; kt++) {
        const int rem = ktiles - 1 - kt;
        if (rem >= 2)      { CP_WAIT(2); }
        else if (rem == 1) { CP_WAIT(1); }
        else               { CP_WAIT(0); }
        __syncthreads();

        // issue next load (overwrites stage (kt-1)&3, which all warps finished)
        if (kt + NSTG - 1 < ktiles) {
            load_tile(kt + NSTG - 1);
            CP_COMMIT();
        }

        const int s = kt & (NSTG - 1);
        const float* sa = sm + s * STG;
        const float* sb = sa + AS;

        #pragma unroll
        for (int kq = 0; kq < 4; kq++) {
            uint32_t af[4][4], bf[4][2];
            #pragma unroll
            for (int mt = 0; mt < 4; mt++) {
                const float* p = sa + (wm + mt * 16 + g) * ROWF + kq * 8 + tig;
                af[mt][0] = __float_as_uint(p[0]);
                af[mt][1] = __float_as_uint(p[8 * ROWF]);
                af[mt][2] = __float_as_uint(p[4]);
                af[mt][3] = __float_as_uint(p[8 * ROWF + 4]);
            }
            #pragma unroll
            for (int nt = 0; nt < 4; nt++) {
                const float* p = sb + (wn + nt * 8 + g) * ROWF + kq * 8 + tig;
                bf[nt][0] = __float_as_uint(p[0]);
                bf[nt][1] = __float_as_uint(p[4]);
            }
            #pragma unroll
            for (int mt = 0; mt < 4; mt++)
                #pragma unroll
                for (int nt = 0; nt < 4; nt++)
                    mma_tf32(acc[mt][nt], af[mt], bf[nt]);
        }
    }

    // ---- fused epilogue ----
    #pragma unroll
    for (int mt = 0; mt < 4; mt++) {
        #pragma unroll
        for (int nt = 0; nt < 4; nt++) {
            const int col = bn + wn + nt * 8 + tig * 2;
            const float bv0 = __ldg(&bias[col]);
            const float bv1 = __ldg(&bias[col + 1]);
            #pragma unroll
            for (int half = 0; half < 2; half++) {
                const int row = bm + wm + mt * 16 + g + half * 8;
                const size_t idx = (size_t)row * N + col;
                const float v0 = acc[mt][nt][half * 2 + 0] + bv0;
                const float v1 = acc[mt][nt][half * 2 + 1] + bv1;
                float2 o, o2;
                if (MODE == 0) {
                    o.x = rtf32(tanhf(v0));
                    o.y = rtf32(tanhf(v1));
                    *reinterpret_cast<float2*>(C + idx) = o;
                } else if (MODE == 1) {
                    const float2 yv = *reinterpret_cast<const float2*>(yin + idx);
                    o.x = v0;  o.y = v1;                           // k1 fp32
                    o2.x = rtf32(yv.x + 0.1f * v0);                // yt rounded
                    o2.y = rtf32(yv.y + 0.1f * v1);
                    *reinterpret_cast<float2*>(C  + idx) = o;
                    *reinterpret_cast<float2*>(C2 + idx) = o2;
                } else {
                    const float2 yv = *reinterpret_cast<const float2*>(yin + idx);
                    const float2 kv = *reinterpret_cast<const float2*>(k1in + idx);
                    o.x = yv.x + 0.05f * (kv.x + v0);              // y_next fp32
                    o.y = yv.y + 0.05f * (kv.y + v1);
                    o2.x = rtf32(o.x);                             // rounded copy
                    o2.y = rtf32(o.y);
                    *reinterpret_cast<float2*>(C  + idx) = o;
                    *reinterpret_cast<float2*>(C2 + idx) = o2;
                }
            }
        }
    }
}

// ---------------- prep kernels ------------------------------------------------
__global__ void transpose_round(const float* __restrict__ in, float* __restrict__ out,
                                int R, int C)
{
    __shared__ float t[32][33];
    const int bx = blockIdx.x * 32, by = blockIdx.y * 32;
    #pragma unroll
    for (int j = 0; j < 32; j += 8)
        t[threadIdx.y + j][threadIdx.x] = in[(size_t)(by + threadIdx.y + j) * C + bx + threadIdx.x];
    __syncthreads();
    #pragma unroll
    for (int j = 0; j < 32; j += 8)
        out[(size_t)(bx + threadIdx.y + j) * R + by + threadIdx.x] =
            rtf32(t[threadIdx.x][threadIdx.y + j]);
}

__global__ void round_copy(const float* __restrict__ in, float* __restrict__ out, int n4)
{
    const int i = blockIdx.x * blockDim.x + threadIdx.x;
    if (i < n4) {
        float4 v = reinterpret_cast<const float4*>(in)[i];
        v.x = rtf32(v.x); v.y = rtf32(v.y); v.z = rtf32(v.z); v.w = rtf32(v.w);
        reinterpret_cast<float4*>(out)[i] = v;
    }
}

// ---------------- launch --------------------------------------------------------
extern "C" void kernel_launch(void* const* d_in, const int* in_sizes, int n_in,
                              void* d_out, int out_size)
{
    const float* y0 = (const float*)d_in[0];
    const float* W1 = (const float*)d_in[1];
    const float* b1 = (const float*)d_in[2];
    const float* W2 = (const float*)d_in[3];
    const float* b2 = (const float*)d_in[4];
    float* out = (float*)d_out;

    float *py, *pyr, *pyt, *pk1, *ph, *pW1t, *pW2t;
    cudaGetSymbolAddress((void**)&py,   g_y);
    cudaGetSymbolAddress((void**)&pyr,  g_yr);
    cudaGetSymbolAddress((void**)&pyt,  g_yt);
    cudaGetSymbolAddress((void**)&pk1,  g_k1);
    cudaGetSymbolAddress((void**)&ph,   g_h);
    cudaGetSymbolAddress((void**)&pW1t, g_W1t);
    cudaGetSymbolAddress((void**)&pW2t, g_W2t);

    cudaFuncSetAttribute(gemm_mma<0>, cudaFuncAttributeMaxDynamicSharedMemorySize, SMEM_TOTAL);
    cudaFuncSetAttribute(gemm_mma<1>, cudaFuncAttributeMaxDynamicSharedMemorySize, SMEM_TOTAL);
    cudaFuncSetAttribute(gemm_mma<2>, cudaFuncAttributeMaxDynamicSharedMemorySize, SMEM_TOTAL);

    // weights -> K-major rounded; y0 -> rounded copy
    transpose_round<<<dim3(H_DIM / 32, D_DIM / 32), dim3(32, 8)>>>(W1, pW1t, D_DIM, H_DIM);
    transpose_round<<<dim3(D_DIM / 32, H_DIM / 32), dim3(32, 8)>>>(W2, pW2t, H_DIM, D_DIM);
    {
        const int n4 = M_BATCH * D_DIM / 4;
        round_copy<<<(n4 + 255) / 256, 256>>>(y0, pyr, n4);
    }

    const dim3 blk(256);
    const dim3 grid1(H_DIM / 128, M_BATCH / 128);   // 16 x 64
    const dim3 grid2(D_DIM / 128, M_BATCH / 128);   //  4 x 64

    const float* ycur = y0;                          // fp32 state input
    for (int s = 0; s < N_STEPS; s++) {
        // k1 pass: h = rtanh(yr@W1t + b1); k1 = h@W2t + b2; yt = round(y + dt*k1)
        gemm_mma<0><<<grid1, blk, SMEM_TOTAL>>>(pyr, pW1t, b1, ph, nullptr, nullptr, nullptr,
                                                H_DIM, D_DIM);
        gemm_mma<1><<<grid2, blk, SMEM_TOTAL>>>(ph, pW2t, b2, pk1, pyt, ycur, nullptr,
                                                D_DIM, H_DIM);
        // k2 pass: h = rtanh(yt@W1t + b1); y = y + 0.05*(k1 + k2); yr = round(y)
        gemm_mma<0><<<grid1, blk, SMEM_TOTAL>>>(pyt, pW1t, b1, ph, nullptr, nullptr, nullptr,
                                                H_DIM, D_DIM);
        float* yo = (s == N_STEPS - 1) ? out : py;
        gemm_mma<2><<<grid2, blk, SMEM_TOTAL>>>(ph, pW2t, b2, yo, pyr, ycur, pk1,
                                                D_DIM, H_DIM);
        ycur = py;
    }
}

// round 4
// speedup vs baseline: 3.6531x; 1.1967x over previous
#include <cuda_runtime.h>
#include <cstdint>
#include <cstddef>

#define M_BATCH 8192
#define D_DIM   512
#define H_DIM   2048
#define N_STEPS 10

// ---------------- scratch (device globals; no allocation allowed) ----------
__device__ float g_y [M_BATCH * D_DIM];            // fp32 state
__device__ float g_yr[M_BATCH * D_DIM];            // tf32-rounded copy of state
__device__ float g_yt[M_BATCH * D_DIM];            // rounded y + dt*k1
__device__ float g_k1[M_BATCH * D_DIM];            // fp32 k1
__device__ float g_h [M_BATCH * H_DIM];            // rounded tanh hidden
__device__ float g_W1t[(size_t)H_DIM * D_DIM];     // W1^T rounded, [N=H, K=D]
__device__ float g_W2t[(size_t)D_DIM * H_DIM];     // W2^T rounded, [N=D, K=H]

// ---------------- helpers ----------------------------------------------------
__device__ __forceinline__ uint32_t smem_u32(const void* p) {
    uint32_t a;
    asm("{ .reg .u64 t; cvta.to.shared.u64 t, %1; cvt.u32.u64 %0, t; }" : "=r"(a) : "l"(p));
    return a;
}
__device__ __forceinline__ float rtf32(float x) {           // round-to-nearest tf32
    uint32_t u;
    asm("cvt.rna.tf32.f32 %0, %1;" : "=r"(u) : "f"(x));
    return __uint_as_float(u);
}
__device__ __forceinline__ float tanh_fast(float x) {       // MUFU.TANH (sm_75+)
    float y;
    asm("tanh.approx.f32 %0, %1;" : "=f"(y) : "f"(x));
    return y;
}
__device__ __forceinline__ void mma_tf32(float c[4], const uint32_t a[4], const uint32_t b[2]) {
    asm volatile(
        "mma.sync.aligned.m16n8k8.row.col.f32.tf32.tf32.f32 "
        "{%0,%1,%2,%3}, {%4,%5,%6,%7}, {%8,%9}, {%0,%1,%2,%3};"
        : "+f"(c[0]), "+f"(c[1]), "+f"(c[2]), "+f"(c[3])
        : "r"(a[0]), "r"(a[1]), "r"(a[2]), "r"(a[3]), "r"(b[0]), "r"(b[1]));
}
#define CP_ASYNC16(dst, src) \
    asm volatile("cp.async.cg.shared.global [%0], [%1], 16;" :: "r"(dst), "l"(src))
#define CP_COMMIT() asm volatile("cp.async.commit_group;" ::: "memory")
#define CP_WAIT(n)  asm volatile("cp.async.wait_group %0;" :: "n"(n) : "memory")

// ---------------- GEMM config ------------------------------------------------
// CTA tile 128x128, BK=32, 3 smem stages, 256 threads (8 warps: 2 m x 4 n, 64x32 each)
// 110,592 B smem/CTA + 128 regs/thr -> 2 CTAs per SM.
constexpr int ROWF  = 36;                 // padded floats per row (144 B, 16B aligned)
constexpr int AS    = 128 * ROWF;         // floats per A (or B) stage
constexpr int STG   = 2 * AS;             // floats per stage (A + B)
constexpr int NSTG  = 3;
constexpr int SMEM_TOTAL = NSTG * STG * 4;  // 110592 B

// MODE 0: C = rtf32(tanh(acc + bias))
// MODE 1: C = acc + bias (k1, fp32);  C2 = rtf32(yin + 0.1*k1)   (yt)
// MODE 2: yn = yin + 0.05*(k1in + (acc+bias)); C = yn (fp32); C2 = rtf32(yn)
template<int MODE>
__global__ void __launch_bounds__(256, 2)
gemm_mma(const float* __restrict__ A,     // [M, K] row-major
         const float* __restrict__ Bw,    // [N, K] row-major (K-major weights)
         const float* __restrict__ bias,
         float* __restrict__ C, float* __restrict__ C2,
         const float* __restrict__ yin, const float* __restrict__ k1in,
         int N, int K)
{
    extern __shared__ float sm[];
    const int tid  = threadIdx.x;
    const int lane = tid & 31;
    const int wid  = tid >> 5;
    const int wm   = (wid & 1) * 64;      // warp m offset in CTA tile
    const int wn   = (wid >> 1) * 32;     // warp n offset
    const int g    = lane >> 2;           // 0..7
    const int tig  = lane & 3;            // 0..3
    const int bm   = blockIdx.y * 128;
    const int bn   = blockIdx.x * 128;
    const int ktiles = K / 32;

    float acc[4][4][4];
    #pragma unroll
    for (int i = 0; i < 4; i++)
        #pragma unroll
        for (int j = 0; j < 4; j++)
            #pragma unroll
            for (int e = 0; e < 4; e++)
                acc[i][j][e] = 0.0f;

    // ---- async tile loader: 128 rows x 32 floats per operand ----
    auto load_tile = [&](int kt) {
        const int s = kt % NSTG;
        float* sa = sm + s * STG;
        float* sb = sa + AS;
        #pragma unroll
        for (int i = 0; i < 4; i++) {
            const int t   = tid + i * 256;       // 0..1023
            const int row = t >> 3;
            const int ch  = t & 7;
            const uint32_t da = smem_u32(sa + row * ROWF + ch * 4);
            CP_ASYNC16(da, A  + (size_t)(bm + row) * K + kt * 32 + ch * 4);
            const uint32_t db = smem_u32(sb + row * ROWF + ch * 4);
            CP_ASYNC16(db, Bw + (size_t)(bn + row) * K + kt * 32 + ch * 4);
        }
    };

    // ---- prologue: 2 stages in flight ----
    #pragma unroll
    for (int kt = 0; kt < NSTG - 1; kt++) {
        if (kt < ktiles) load_tile(kt);
        CP_COMMIT();
    }

    // ---- mainloop ----
    for (int kt = 0; kt < ktiles; kt++) {
        if (kt + 1 < ktiles) { CP_WAIT(1); }
        else                 { CP_WAIT(0); }
        __syncthreads();

        // issue next load (overwrites stage (kt-1)%3, which all warps finished)
        if (kt + NSTG - 1 < ktiles) {
            load_tile(kt + NSTG - 1);
            CP_COMMIT();
        }

        const int s = kt % NSTG;
        const float* sa = sm + s * STG;
        const float* sb = sa + AS;

        #pragma unroll
        for (int kq = 0; kq < 4; kq++) {
            uint32_t af[4][4], bf[4][2];
            #pragma unroll
            for (int mt = 0; mt < 4; mt++) {
                const float* p = sa + (wm + mt * 16 + g) * ROWF + kq * 8 + tig;
                af[mt][0] = __float_as_uint(p[0]);
                af[mt][1] = __float_as_uint(p[8 * ROWF]);
                af[mt][2] = __float_as_uint(p[4]);
                af[mt][3] = __float_as_uint(p[8 * ROWF + 4]);
            }
            #pragma unroll
            for (int nt = 0; nt < 4; nt++) {
                const float* p = sb + (wn + nt * 8 + g) * ROWF + kq * 8 + tig;
                bf[nt][0] = __float_as_uint(p[0]);
                bf[nt][1] = __float_as_uint(p[4]);
            }
            #pragma unroll
            for (int mt = 0; mt < 4; mt++)
                #pragma unroll
                for (int nt = 0; nt < 4; nt++)
                    mma_tf32(acc[mt][nt], af[mt], bf[nt]);
        }
    }

    // ---- fused epilogue ----
    #pragma unroll
    for (int mt = 0; mt < 4; mt++) {
        #pragma unroll
        for (int nt = 0; nt < 4; nt++) {
            const int col = bn + wn + nt * 8 + tig * 2;
            const float bv0 = __ldg(&bias[col]);
            const float bv1 = __ldg(&bias[col + 1]);
            #pragma unroll
            for (int half = 0; half < 2; half++) {
                const int row = bm + wm + mt * 16 + g + half * 8;
                const size_t idx = (size_t)row * N + col;
                const float v0 = acc[mt][nt][half * 2 + 0] + bv0;
                const float v1 = acc[mt][nt][half * 2 + 1] + bv1;
                float2 o, o2;
                if (MODE == 0) {
                    o.x = rtf32(tanh_fast(v0));
                    o.y = rtf32(tanh_fast(v1));
                    *reinterpret_cast<float2*>(C + idx) = o;
                } else if (MODE == 1) {
                    const float2 yv = *reinterpret_cast<const float2*>(yin + idx);
                    o.x = v0;  o.y = v1;                           // k1 fp32
                    o2.x = rtf32(yv.x + 0.1f * v0);                // yt rounded
                    o2.y = rtf32(yv.y + 0.1f * v1);
                    *reinterpret_cast<float2*>(C  + idx) = o;
                    *reinterpret_cast<float2*>(C2 + idx) = o2;
                } else {
                    const float2 yv = *reinterpret_cast<const float2*>(yin + idx);
                    const float2 kv = *reinterpret_cast<const float2*>(k1in + idx);
                    o.x = yv.x + 0.05f * (kv.x + v0);              // y_next fp32
                    o.y = yv.y + 0.05f * (kv.y + v1);
                    o2.x = rtf32(o.x);                             // rounded copy
                    o2.y = rtf32(o.y);
                    *reinterpret_cast<float2*>(C  + idx) = o;
                    *reinterpret_cast<float2*>(C2 + idx) = o2;
                }
            }
        }
    }
}

// ---------------- prep kernels ------------------------------------------------
__global__ void transpose_round(const float* __restrict__ in, float* __restrict__ out,
                                int R, int C)
{
    __shared__ float t[32][33];
    const int bx = blockIdx.x * 32, by = blockIdx.y * 32;
    #pragma unroll
    for (int j = 0; j < 32; j += 8)
        t[threadIdx.y + j][threadIdx.x] = in[(size_t)(by + threadIdx.y + j) * C + bx + threadIdx.x];
    __syncthreads();
    #pragma unroll
    for (int j = 0; j < 32; j += 8)
        out[(size_t)(bx + threadIdx.y + j) * R + by + threadIdx.x] =
            rtf32(t[threadIdx.x][threadIdx.y + j]);
}

__global__ void round_copy(const float* __restrict__ in, float* __restrict__ out, int n4)
{
    const int i = blockIdx.x * blockDim.x + threadIdx.x;
    if (i < n4) {
        float4 v = reinterpret_cast<const float4*>(in)[i];
        v.x = rtf32(v.x); v.y = rtf32(v.y); v.z = rtf32(v.z); v.w = rtf32(v.w);
        reinterpret_cast<float4*>(out)[i] = v;
    }
}

// ---------------- launch --------------------------------------------------------
extern "C" void kernel_launch(void* const* d_in, const int* in_sizes, int n_in,
                              void* d_out, int out_size)
{
    const float* y0 = (const float*)d_in[0];
    const float* W1 = (const float*)d_in[1];
    const float* b1 = (const float*)d_in[2];
    const float* W2 = (const float*)d_in[3];
    const float* b2 = (const float*)d_in[4];
    float* out = (float*)d_out;

    float *py, *pyr, *pyt, *pk1, *ph, *pW1t, *pW2t;
    cudaGetSymbolAddress((void**)&py,   g_y);
    cudaGetSymbolAddress((void**)&pyr,  g_yr);
    cudaGetSymbolAddress((void**)&pyt,  g_yt);
    cudaGetSymbolAddress((void**)&pk1,  g_k1);
    cudaGetSymbolAddress((void**)&ph,   g_h);
    cudaGetSymbolAddress((void**)&pW1t, g_W1t);
    cudaGetSymbolAddress((void**)&pW2t, g_W2t);

    cudaFuncSetAttribute(gemm_mma<0>, cudaFuncAttributeMaxDynamicSharedMemorySize, SMEM_TOTAL);
    cudaFuncSetAttribute(gemm_mma<1>, cudaFuncAttributeMaxDynamicSharedMemorySize, SMEM_TOTAL);
    cudaFuncSetAttribute(gemm_mma<2>, cudaFuncAttributeMaxDynamicSharedMemorySize, SMEM_TOTAL);

    // weights -> K-major rounded; y0 -> rounded copy
    transpose_round<<<dim3(H_DIM / 32, D_DIM / 32), dim3(32, 8)>>>(W1, pW1t, D_DIM, H_DIM);
    transpose_round<<<dim3(D_DIM / 32, H_DIM / 32), dim3(32, 8)>>>(W2, pW2t, H_DIM, D_DIM);
    {
        const int n4 = M_BATCH * D_DIM / 4;
        round_copy<<<(n4 + 255) / 256, 256>>>(y0, pyr, n4);
    }

    const dim3 blk(256);
    const dim3 grid1(H_DIM / 128, M_BATCH / 128);   // 16 x 64
    const dim3 grid2(D_DIM / 128, M_BATCH / 128);   //  4 x 64

    const float* ycur = y0;                          // fp32 state input
    for (int s = 0; s < N_STEPS; s++) {
        // k1 pass: h = rtanh(yr@W1t + b1); k1 = h@W2t + b2; yt = round(y + dt*k1)
        gemm_mma<0><<<grid1, blk, SMEM_TOTAL>>>(pyr, pW1t, b1, ph, nullptr, nullptr, nullptr,
                                                H_DIM, D_DIM);
        gemm_mma<1><<<grid2, blk, SMEM_TOTAL>>>(ph, pW2t, b2, pk1, pyt, ycur, nullptr,
                                                D_DIM, H_DIM);
        // k2 pass: h = rtanh(yt@W1t + b1); y = y + 0.05*(k1 + k2); yr = round(y)
        gemm_mma<0><<<grid1, blk, SMEM_TOTAL>>>(pyt, pW1t, b1, ph, nullptr, nullptr, nullptr,
                                                H_DIM, D_DIM);
        float* yo = (s == N_STEPS - 1) ? out : py;
        gemm_mma<2><<<grid2, blk, SMEM_TOTAL>>>(ph, pW2t, b2, yo, pyr, ycur, pk1,
                                                D_DIM, H_DIM);
        ycur = py;
    }
}

// round 5
// speedup vs baseline: 7.5833x; 2.0759x over previous
#include <cuda_runtime.h>
#include <cuda_fp16.h>
#include <cstdint>
#include <cstddef>

#define M_BATCH 8192
#define D_DIM   512
#define H_DIM   2048
#define N_STEPS 10

// ---------------- scratch (device globals; no allocation allowed) ----------
__device__ float  g_y [M_BATCH * D_DIM];            // fp32 state
__device__ float  g_k1[M_BATCH * D_DIM];            // fp32 k1
__device__ __half g_yr[M_BATCH * D_DIM];            // fp16 copy of state (GEMM1 A)
__device__ __half g_yt[M_BATCH * D_DIM];            // fp16 y + dt*k1   (GEMM1 A)
__device__ __half g_h [M_BATCH * H_DIM];            // fp16 tanh hidden (GEMM2 A)
__device__ __half g_W1t[(size_t)H_DIM * D_DIM];     // W1^T fp16, [N=H, K=D]
__device__ __half g_W2t[(size_t)D_DIM * H_DIM];     // W2^T fp16, [N=D, K=H]

// ---------------- helpers ----------------------------------------------------
__device__ __forceinline__ uint32_t smem_u32(const void* p) {
    uint32_t a;
    asm("{ .reg .u64 t; cvta.to.shared.u64 t, %1; cvt.u32.u64 %0, t; }" : "=r"(a) : "l"(p));
    return a;
}
__device__ __forceinline__ float tanh_fast(float x) {       // MUFU.TANH
    float y;
    asm("tanh.approx.f32 %0, %1;" : "=f"(y) : "f"(x));
    return y;
}
__device__ __forceinline__ void mma_f16(float c[4], const uint32_t a[4], const uint32_t b[2]) {
    asm volatile(
        "mma.sync.aligned.m16n8k16.row.col.f32.f16.f16.f32 "
        "{%0,%1,%2,%3}, {%4,%5,%6,%7}, {%8,%9}, {%0,%1,%2,%3};"
        : "+f"(c[0]), "+f"(c[1]), "+f"(c[2]), "+f"(c[3])
        : "r"(a[0]), "r"(a[1]), "r"(a[2]), "r"(a[3]), "r"(b[0]), "r"(b[1]));
}
#define CP_ASYNC16(dst, src) \
    asm volatile("cp.async.cg.shared.global [%0], [%1], 16;" :: "r"(dst), "l"(src))
#define CP_COMMIT() asm volatile("cp.async.commit_group;" ::: "memory")
#define CP_WAIT(n)  asm volatile("cp.async.wait_group %0;" :: "n"(n) : "memory")

// ---------------- GEMM config ------------------------------------------------
// CTA tile 128x128, BK=64 (fp16), 3 smem stages, 256 threads (8 warps: 2m x 4n).
// Rows are 128B (64 halves) with XOR-16B-chunk swizzle: chunk' = chunk ^ (row&7).
constexpr int ROWB  = 128;                 // bytes per smem row
constexpr int ASZ   = 128 * ROWB;          // 16384 B per operand stage
constexpr int STGB  = 2 * ASZ;             // 32768 B per stage (A + B)
constexpr int NSTG  = 3;
constexpr int SMEM_TOTAL = NSTG * STGB;    // 98304 B -> 2 CTAs/SM

// byte offset of half-index h (0..63) in swizzled row `row`
__device__ __forceinline__ uint32_t swz(int row, int h) {
    return (uint32_t)(row * ROWB + (((h >> 3) ^ (row & 7)) << 4) + (h & 7) * 2);
}

// MODE 0: Ch = fp16(tanh(acc + bias))
// MODE 1: Cf = acc + bias (k1, fp32);  C2h = fp16(yin + 0.1*k1)   (yt)
// MODE 2: yn = yin + 0.05*(k1in + (acc+bias)); Cf = yn (fp32); C2h = fp16(yn)
template<int MODE>
__global__ void __launch_bounds__(256, 2)
gemm_mma(const __half* __restrict__ A,     // [M, K] row-major fp16
         const __half* __restrict__ Bw,    // [N, K] row-major fp16 (K-major weights)
         const float* __restrict__ bias,
         float* __restrict__ Cf, __half* __restrict__ Ch, __half* __restrict__ C2h,
         const float* __restrict__ yin, const float* __restrict__ k1in,
         int N, int K)
{
    extern __shared__ char sm[];
    const int tid  = threadIdx.x;
    const int lane = tid & 31;
    const int wid  = tid >> 5;
    const int wm   = (wid & 1) * 64;      // warp m offset
    const int wn   = (wid >> 1) * 32;     // warp n offset
    const int g    = lane >> 2;           // 0..7
    const int tig  = lane & 3;            // 0..3
    const int bm   = blockIdx.y * 128;
    const int bn   = blockIdx.x * 128;
    const int ktiles = K / 64;

    float acc[4][4][4];
    #pragma unroll
    for (int i = 0; i < 4; i++)
        #pragma unroll
        for (int j = 0; j < 4; j++)
            #pragma unroll
            for (int e = 0; e < 4; e++)
                acc[i][j][e] = 0.0f;

    // ---- async tile loader: 128 rows x 64 halves (8 x 16B chunks) per operand
    auto load_tile = [&](int kt) {
        const int s = kt % NSTG;
        char* sa = sm + s * STGB;
        char* sb = sa + ASZ;
        #pragma unroll
        for (int i = 0; i < 4; i++) {
            const int t   = tid + i * 256;       // 0..1023
            const int row = t >> 3;
            const int ch  = t & 7;
            const uint32_t off = (uint32_t)(row * ROWB + ((ch ^ (row & 7)) << 4));
            CP_ASYNC16(smem_u32(sa + off), A  + (size_t)(bm + row) * K + kt * 64 + ch * 8);
            CP_ASYNC16(smem_u32(sb + off), Bw + (size_t)(bn + row) * K + kt * 64 + ch * 8);
        }
    };

    // ---- prologue: 2 stages in flight ----
    #pragma unroll
    for (int kt = 0; kt < NSTG - 1; kt++) {
        if (kt < ktiles) load_tile(kt);
        CP_COMMIT();
    }

    // ---- mainloop ----
    for (int kt = 0; kt < ktiles; kt++) {
        if (kt + 1 < ktiles) { CP_WAIT(1); }
        else                 { CP_WAIT(0); }
        __syncthreads();

        if (kt + NSTG - 1 < ktiles) {
            load_tile(kt + NSTG - 1);
            CP_COMMIT();
        }

        const int s = kt % NSTG;
        const char* sa = sm + s * STGB;
        const char* sb = sa + ASZ;

        #pragma unroll
        for (int kq = 0; kq < 4; kq++) {          // 4 x k16
            uint32_t af[4][4], bf[4][2];
            const int h0 = kq * 16 + 2 * tig;     // k half-index of first pair
            #pragma unroll
            for (int mt = 0; mt < 4; mt++) {
                const int r0 = wm + mt * 16 + g;
                af[mt][0] = *(const uint32_t*)(sa + swz(r0,     h0));
                af[mt][1] = *(const uint32_t*)(sa + swz(r0 + 8, h0));
                af[mt][2] = *(const uint32_t*)(sa + swz(r0,     h0 + 8));
                af[mt][3] = *(const uint32_t*)(sa + swz(r0 + 8, h0 + 8));
            }
            #pragma unroll
            for (int nt = 0; nt < 4; nt++) {
                const int rn = wn + nt * 8 + g;
                bf[nt][0] = *(const uint32_t*)(sb + swz(rn, h0));
                bf[nt][1] = *(const uint32_t*)(sb + swz(rn, h0 + 8));
            }
            #pragma unroll
            for (int mt = 0; mt < 4; mt++)
                #pragma unroll
                for (int nt = 0; nt < 4; nt++)
                    mma_f16(acc[mt][nt], af[mt], bf[nt]);
        }
    }

    // ---- fused epilogue ----
    #pragma unroll
    for (int mt = 0; mt < 4; mt++) {
        #pragma unroll
        for (int nt = 0; nt < 4; nt++) {
            const int col = bn + wn + nt * 8 + tig * 2;
            const float bv0 = __ldg(&bias[col]);
            const float bv1 = __ldg(&bias[col + 1]);
            #pragma unroll
            for (int half = 0; half < 2; half++) {
                const int row = bm + wm + mt * 16 + g + half * 8;
                const size_t idx = (size_t)row * N + col;
                const float v0 = acc[mt][nt][half * 2 + 0] + bv0;
                const float v1 = acc[mt][nt][half * 2 + 1] + bv1;
                if (MODE == 0) {
                    *reinterpret_cast<__half2*>(Ch + idx) =
                        __floats2half2_rn(tanh_fast(v0), tanh_fast(v1));
                } else if (MODE == 1) {
                    const float2 yv = *reinterpret_cast<const float2*>(yin + idx);
                    float2 o;  o.x = v0;  o.y = v1;                    // k1 fp32
                    *reinterpret_cast<float2*>(Cf + idx) = o;
                    *reinterpret_cast<__half2*>(C2h + idx) =
                        __floats2half2_rn(yv.x + 0.1f * v0, yv.y + 0.1f * v1);
                } else {
                    const float2 yv = *reinterpret_cast<const float2*>(yin + idx);
                    const float2 kv = *reinterpret_cast<const float2*>(k1in + idx);
                    float2 o;
                    o.x = yv.x + 0.05f * (kv.x + v0);                  // y_next fp32
                    o.y = yv.y + 0.05f * (kv.y + v1);
                    *reinterpret_cast<float2*>(Cf + idx) = o;
                    *reinterpret_cast<__half2*>(C2h + idx) = __floats2half2_rn(o.x, o.y);
                }
            }
        }
    }
}

// ---------------- prep kernels ------------------------------------------------
__global__ void transpose_half(const float* __restrict__ in, __half* __restrict__ out,
                               int R, int C)
{
    __shared__ float t[32][33];
    const int bx = blockIdx.x * 32, by = blockIdx.y * 32;
    #pragma unroll
    for (int j = 0; j < 32; j += 8)
        t[threadIdx.y + j][threadIdx.x] = in[(size_t)(by + threadIdx.y + j) * C + bx + threadIdx.x];
    __syncthreads();
    #pragma unroll
    for (int j = 0; j < 32; j += 8)
        out[(size_t)(bx + threadIdx.y + j) * R + by + threadIdx.x] =
            __float2half_rn(t[threadIdx.x][threadIdx.y + j]);
}

__global__ void half_copy(const float* __restrict__ in, __half* __restrict__ out, int n4)
{
    const int i = blockIdx.x * blockDim.x + threadIdx.x;
    if (i < n4) {
        const float4 v = reinterpret_cast<const float4*>(in)[i];
        __half2 h0 = __floats2half2_rn(v.x, v.y);
        __half2 h1 = __floats2half2_rn(v.z, v.w);
        reinterpret_cast<__half2*>(out)[i * 2 + 0] = h0;
        reinterpret_cast<__half2*>(out)[i * 2 + 1] = h1;
    }
}

// ---------------- launch --------------------------------------------------------
extern "C" void kernel_launch(void* const* d_in, const int* in_sizes, int n_in,
                              void* d_out, int out_size)
{
    const float* y0 = (const float*)d_in[0];
    const float* W1 = (const float*)d_in[1];
    const float* b1 = (const float*)d_in[2];
    const float* W2 = (const float*)d_in[3];
    const float* b2 = (const float*)d_in[4];
    float* out = (float*)d_out;

    float *py, *pk1;
    __half *pyr, *pyt, *ph, *pW1t, *pW2t;
    cudaGetSymbolAddress((void**)&py,   g_y);
    cudaGetSymbolAddress((void**)&pk1,  g_k1);
    cudaGetSymbolAddress((void**)&pyr,  g_yr);
    cudaGetSymbolAddress((void**)&pyt,  g_yt);
    cudaGetSymbolAddress((void**)&ph,   g_h);
    cudaGetSymbolAddress((void**)&pW1t, g_W1t);
    cudaGetSymbolAddress((void**)&pW2t, g_W2t);

    cudaFuncSetAttribute(gemm_mma<0>, cudaFuncAttributeMaxDynamicSharedMemorySize, SMEM_TOTAL);
    cudaFuncSetAttribute(gemm_mma<1>, cudaFuncAttributeMaxDynamicSharedMemorySize, SMEM_TOTAL);
    cudaFuncSetAttribute(gemm_mma<2>, cudaFuncAttributeMaxDynamicSharedMemorySize, SMEM_TOTAL);

    // weights -> K-major fp16; y0 -> fp16 copy
    transpose_half<<<dim3(H_DIM / 32, D_DIM / 32), dim3(32, 8)>>>(W1, pW1t, D_DIM, H_DIM);
    transpose_half<<<dim3(D_DIM / 32, H_DIM / 32), dim3(32, 8)>>>(W2, pW2t, H_DIM, D_DIM);
    {
        const int n4 = M_BATCH * D_DIM / 4;
        half_copy<<<(n4 + 255) / 256, 256>>>(y0, pyr, n4);
    }

    const dim3 blk(256);
    const dim3 grid1(H_DIM / 128, M_BATCH / 128);   // 16 x 64
    const dim3 grid2(D_DIM / 128, M_BATCH / 128);   //  4 x 64

    const float* ycur = y0;                          // fp32 state input
    for (int s = 0; s < N_STEPS; s++) {
        // k1 pass: h = tanh(yr@W1t + b1); k1 = h@W2t + b2; yt = fp16(y + dt*k1)
        gemm_mma<0><<<grid1, blk, SMEM_TOTAL>>>(pyr, pW1t, b1, nullptr, ph, nullptr,
                                                nullptr, nullptr, H_DIM, D_DIM);
        gemm_mma<1><<<grid2, blk, SMEM_TOTAL>>>(ph, pW2t, b2, pk1, nullptr, pyt,
                                                ycur, nullptr, D_DIM, H_DIM);
        // k2 pass: h = tanh(yt@W1t + b1); y = y + 0.05*(k1 + k2); yr = fp16(y)
        gemm_mma<0><<<grid1, blk, SMEM_TOTAL>>>(pyt, pW1t, b1, nullptr, ph, nullptr,
                                                nullptr, nullptr, H_DIM, D_DIM);
        float* yo = (s == N_STEPS - 1) ? out : py;
        gemm_mma<2><<<grid2, blk, SMEM_TOTAL>>>(ph, pW2t, b2, yo, nullptr, pyr,
                                                ycur, pk1, D_DIM, H_DIM);
        ycur = py;
    }
}

// round 6
// speedup vs baseline: 8.1178x; 1.0705x over previous
#include <cuda_runtime.h>
#include <cuda_fp16.h>
#include <cstdint>
#include <cstddef>

#define M_BATCH 8192
#define D_DIM   512
#define H_DIM   2048
#define N_STEPS 10

// ---------------- scratch (device globals; no allocation allowed) ----------
__device__ float  g_y [M_BATCH * D_DIM];            // fp32 state
__device__ float  g_k1[M_BATCH * D_DIM];            // fp32 k1
__device__ __half g_yr[M_BATCH * D_DIM];            // fp16 copy of state (GEMM1 A)
__device__ __half g_yt[M_BATCH * D_DIM];            // fp16 y + dt*k1   (GEMM1 A)
__device__ __half g_h [M_BATCH * H_DIM];            // fp16 tanh hidden (GEMM2 A)
__device__ __half g_W1t[(size_t)H_DIM * D_DIM];     // W1^T fp16, [N=H, K=D]
__device__ __half g_W2t[(size_t)D_DIM * H_DIM];     // W2^T fp16, [N=D, K=H]

// ---------------- helpers ----------------------------------------------------
__device__ __forceinline__ uint32_t smem_u32(const void* p) {
    uint32_t a;
    asm("{ .reg .u64 t; cvta.to.shared.u64 t, %1; cvt.u32.u64 %0, t; }" : "=r"(a) : "l"(p));
    return a;
}
__device__ __forceinline__ float tanh_fast(float x) {       // MUFU.TANH
    float y;
    asm("tanh.approx.f32 %0, %1;" : "=f"(y) : "f"(x));
    return y;
}
__device__ __forceinline__ void mma_f16(float c[4], const uint32_t a[4], const uint32_t b[2]) {
    asm volatile(
        "mma.sync.aligned.m16n8k16.row.col.f32.f16.f16.f32 "
        "{%0,%1,%2,%3}, {%4,%5,%6,%7}, {%8,%9}, {%0,%1,%2,%3};"
        : "+f"(c[0]), "+f"(c[1]), "+f"(c[2]), "+f"(c[3])
        : "r"(a[0]), "r"(a[1]), "r"(a[2]), "r"(a[3]), "r"(b[0]), "r"(b[1]));
}
__device__ __forceinline__ void ldsm_x4(uint32_t r[4], uint32_t addr) {
    asm volatile("ldmatrix.sync.aligned.m8n8.x4.shared.b16 {%0,%1,%2,%3}, [%4];"
        : "=r"(r[0]), "=r"(r[1]), "=r"(r[2]), "=r"(r[3]) : "r"(addr));
}
#define CP_ASYNC16(dst, src) \
    asm volatile("cp.async.cg.shared.global [%0], [%1], 16;" :: "r"(dst), "l"(src))
#define CP_COMMIT() asm volatile("cp.async.commit_group;" ::: "memory")
#define CP_WAIT(n)  asm volatile("cp.async.wait_group %0;" :: "n"(n) : "memory")

// ---------------- GEMM config ------------------------------------------------
// CTA tile 128x128, BK=64 (fp16), 3 smem stages, 256 threads (8 warps: 2m x 4n).
// Rows are 128B (64 halves) with XOR-16B-chunk swizzle: chunk' = chunk ^ (row&7).
constexpr int ROWB  = 128;                 // bytes per smem row
constexpr int ASZ   = 128 * ROWB;          // 16384 B per operand stage
constexpr int STGB  = 2 * ASZ;             // 32768 B per stage (A + B)
constexpr int NSTG  = 3;
constexpr int SMEM_TOTAL = NSTG * STGB;    // 98304 B -> 2 CTAs/SM

// MODE 0: Ch = fp16(tanh(acc + bias))
// MODE 1: Cf = acc + bias (k1, fp32);  C2h = fp16(yin + 0.1*k1)   (yt)
// MODE 2: yn = yin + 0.05*(k1in + (acc+bias)); Cf = yn (fp32); C2h = fp16(yn)
template<int MODE>
__global__ void __launch_bounds__(256, 2)
gemm_mma(const __half* __restrict__ A,     // [M, K] row-major fp16
         const __half* __restrict__ Bw,    // [N, K] row-major fp16 (K-major weights)
         const float* __restrict__ bias,
         float* __restrict__ Cf, __half* __restrict__ Ch, __half* __restrict__ C2h,
         const float* __restrict__ yin, const float* __restrict__ k1in,
         int N, int K)
{
    extern __shared__ char sm[];
    const uint32_t smb = smem_u32(sm);
    const int tid  = threadIdx.x;
    const int lane = tid & 31;
    const int wid  = tid >> 5;
    const int wm   = (wid & 1) * 64;      // warp m offset
    const int wn   = (wid >> 1) * 32;     // warp n offset
    const int g    = lane >> 2;           // 0..7 (epilogue row group)
    const int tig  = lane & 3;            // 0..3
    const int bm   = blockIdx.y * 128;
    const int bn   = blockIdx.x * 128;
    const int ktiles = K / 64;

    // ldmatrix lane decomposition
    const int e  = lane & 7;               // row-within-8 (== row&7 of every target row)
    const int m  = lane >> 3;              // matrix index 0..3
    // A: rows (m&1)*8+e, chunk parity m>>1 ; B: rows (m>>1)*8+e, chunk parity m&1
    const uint32_t rowA = (uint32_t)(wm + (m & 1) * 8 + e) * ROWB;   // + mt*16*ROWB
    const int      ca   = m >> 1;
    const uint32_t rowB = (uint32_t)(wn + (m >> 1) * 8 + e) * ROWB;  // + ntp*16*ROWB
    const int      cb   = m & 1;

    float acc[4][4][4];
    #pragma unroll
    for (int i = 0; i < 4; i++)
        #pragma unroll
        for (int j = 0; j < 4; j++)
            #pragma unroll
            for (int el = 0; el < 4; el++)
                acc[i][j][el] = 0.0f;

    // ---- async tile loader: 128 rows x 64 halves (8 x 16B chunks) per operand
    auto load_tile = [&](int kt) {
        const int s = kt % NSTG;
        const uint32_t sa = smb + s * STGB;
        const uint32_t sb = sa + ASZ;
        #pragma unroll
        for (int i = 0; i < 4; i++) {
            const int t   = tid + i * 256;       // 0..1023
            const int row = t >> 3;
            const int ch  = t & 7;
            const uint32_t off = (uint32_t)(row * ROWB + ((ch ^ (row & 7)) << 4));
            CP_ASYNC16(sa + off, A  + (size_t)(bm + row) * K + kt * 64 + ch * 8);
            CP_ASYNC16(sb + off, Bw + (size_t)(bn + row) * K + kt * 64 + ch * 8);
        }
    };

    // ---- prologue: 2 stages in flight ----
    #pragma unroll
    for (int kt = 0; kt < NSTG - 1; kt++) {
        if (kt < ktiles) load_tile(kt);
        CP_COMMIT();
    }

    // ---- mainloop ----
    for (int kt = 0; kt < ktiles; kt++) {
        if (kt + 1 < ktiles) { CP_WAIT(1); }
        else                 { CP_WAIT(0); }
        __syncthreads();

        if (kt + NSTG - 1 < ktiles) {
            load_tile(kt + NSTG - 1);
            CP_COMMIT();
        }

        const int s = kt % NSTG;
        const uint32_t sa = smb + s * STGB;
        const uint32_t sb = sa + ASZ;

        #pragma unroll
        for (int kq = 0; kq < 4; kq++) {          // 4 x k16
            uint32_t af[4][4], bf[4][2];
            // A fragments: 4 x ldmatrix.x4 (one per mt)
            #pragma unroll
            for (int mt = 0; mt < 4; mt++) {
                const uint32_t addr = sa + rowA + (uint32_t)(mt * 16) * ROWB
                                    + (uint32_t)(((2 * kq + ca) ^ e) << 4);
                ldsm_x4(af[mt], addr);
            }
            // B fragments: 2 x ldmatrix.x4 (each covers two n-tiles)
            #pragma unroll
            for (int ntp = 0; ntp < 2; ntp++) {
                uint32_t r[4];
                const uint32_t addr = sb + rowB + (uint32_t)(ntp * 16) * ROWB
                                    + (uint32_t)(((2 * kq + cb) ^ e) << 4);
                ldsm_x4(r, addr);
                bf[2 * ntp + 0][0] = r[0];
                bf[2 * ntp + 0][1] = r[1];
                bf[2 * ntp + 1][0] = r[2];
                bf[2 * ntp + 1][1] = r[3];
            }
            #pragma unroll
            for (int mt = 0; mt < 4; mt++)
                #pragma unroll
                for (int nt = 0; nt < 4; nt++)
                    mma_f16(acc[mt][nt], af[mt], bf[nt]);
        }
    }

    // ---- fused epilogue ----
    #pragma unroll
    for (int mt = 0; mt < 4; mt++) {
        #pragma unroll
        for (int nt = 0; nt < 4; nt++) {
            const int col = bn + wn + nt * 8 + tig * 2;
            const float bv0 = __ldg(&bias[col]);
            const float bv1 = __ldg(&bias[col + 1]);
            #pragma unroll
            for (int half = 0; half < 2; half++) {
                const int row = bm + wm + mt * 16 + g + half * 8;
                const size_t idx = (size_t)row * N + col;
                const float v0 = acc[mt][nt][half * 2 + 0] + bv0;
                const float v1 = acc[mt][nt][half * 2 + 1] + bv1;
                if (MODE == 0) {
                    *reinterpret_cast<__half2*>(Ch + idx) =
                        __floats2half2_rn(tanh_fast(v0), tanh_fast(v1));
                } else if (MODE == 1) {
                    const float2 yv = *reinterpret_cast<const float2*>(yin + idx);
                    float2 o;  o.x = v0;  o.y = v1;                    // k1 fp32
                    *reinterpret_cast<float2*>(Cf + idx) = o;
                    *reinterpret_cast<__half2*>(C2h + idx) =
                        __floats2half2_rn(yv.x + 0.1f * v0, yv.y + 0.1f * v1);
                } else {
                    const float2 yv = *reinterpret_cast<const float2*>(yin + idx);
                    const float2 kv = *reinterpret_cast<const float2*>(k1in + idx);
                    float2 o;
                    o.x = yv.x + 0.05f * (kv.x + v0);                  // y_next fp32
                    o.y = yv.y + 0.05f * (kv.y + v1);
                    *reinterpret_cast<float2*>(Cf + idx) = o;
                    *reinterpret_cast<__half2*>(C2h + idx) = __floats2half2_rn(o.x, o.y);
                }
            }
        }
    }
}

// ---------------- prep kernels ------------------------------------------------
__global__ void transpose_half(const float* __restrict__ in, __half* __restrict__ out,
                               int R, int C)
{
    __shared__ float t[32][33];
    const int bx = blockIdx.x * 32, by = blockIdx.y * 32;
    #pragma unroll
    for (int j = 0; j < 32; j += 8)
        t[threadIdx.y + j][threadIdx.x] = in[(size_t)(by + threadIdx.y + j) * C + bx + threadIdx.x];
    __syncthreads();
    #pragma unroll
    for (int j = 0; j < 32; j += 8)
        out[(size_t)(bx + threadIdx.y + j) * R + by + threadIdx.x] =
            __float2half_rn(t[threadIdx.x][threadIdx.y + j]);
}

__global__ void half_copy(const float* __restrict__ in, __half* __restrict__ out, int n4)
{
    const int i = blockIdx.x * blockDim.x + threadIdx.x;
    if (i < n4) {
        const float4 v = reinterpret_cast<const float4*>(in)[i];
        __half2 h0 = __floats2half2_rn(v.x, v.y);
        __half2 h1 = __floats2half2_rn(v.z, v.w);
        reinterpret_cast<__half2*>(out)[i * 2 + 0] = h0;
        reinterpret_cast<__half2*>(out)[i * 2 + 1] = h1;
    }
}

// ---------------- launch --------------------------------------------------------
extern "C" void kernel_launch(void* const* d_in, const int* in_sizes, int n_in,
                              void* d_out, int out_size)
{
    const float* y0 = (const float*)d_in[0];
    const float* W1 = (const float*)d_in[1];
    const float* b1 = (const float*)d_in[2];
    const float* W2 = (const float*)d_in[3];
    const float* b2 = (const float*)d_in[4];
    float* out = (float*)d_out;

    float *py, *pk1;
    __half *pyr, *pyt, *ph, *pW1t, *pW2t;
    cudaGetSymbolAddress((void**)&py,   g_y);
    cudaGetSymbolAddress((void**)&pk1,  g_k1);
    cudaGetSymbolAddress((void**)&pyr,  g_yr);
    cudaGetSymbolAddress((void**)&pyt,  g_yt);
    cudaGetSymbolAddress((void**)&ph,   g_h);
    cudaGetSymbolAddress((void**)&pW1t, g_W1t);
    cudaGetSymbolAddress((void**)&pW2t, g_W2t);

    cudaFuncSetAttribute(gemm_mma<0>, cudaFuncAttributeMaxDynamicSharedMemorySize, SMEM_TOTAL);
    cudaFuncSetAttribute(gemm_mma<1>, cudaFuncAttributeMaxDynamicSharedMemorySize, SMEM_TOTAL);
    cudaFuncSetAttribute(gemm_mma<2>, cudaFuncAttributeMaxDynamicSharedMemorySize, SMEM_TOTAL);

    // weights -> K-major fp16; y0 -> fp16 copy
    transpose_half<<<dim3(H_DIM / 32, D_DIM / 32), dim3(32, 8)>>>(W1, pW1t, D_DIM, H_DIM);
    transpose_half<<<dim3(D_DIM / 32, H_DIM / 32), dim3(32, 8)>>>(W2, pW2t, H_DIM, D_DIM);
    {
        const int n4 = M_BATCH * D_DIM / 4;
        half_copy<<<(n4 + 255) / 256, 256>>>(y0, pyr, n4);
    }

    const dim3 blk(256);
    const dim3 grid1(H_DIM / 128, M_BATCH / 128);   // 16 x 64
    const dim3 grid2(D_DIM / 128, M_BATCH / 128);   //  4 x 64

    const float* ycur = y0;                          // fp32 state input
    for (int s = 0; s < N_STEPS; s++) {
        // k1 pass: h = tanh(yr@W1t + b1); k1 = h@W2t + b2; yt = fp16(y + dt*k1)
        gemm_mma<0><<<grid1, blk, SMEM_TOTAL>>>(pyr, pW1t, b1, nullptr, ph, nullptr,
                                                nullptr, nullptr, H_DIM, D_DIM);
        gemm_mma<1><<<grid2, blk, SMEM_TOTAL>>>(ph, pW2t, b2, pk1, nullptr, pyt,
                                                ycur, nullptr, D_DIM, H_DIM);
        // k2 pass: h = tanh(yt@W1t + b1); y = y + 0.05*(k1 + k2); yr = fp16(y)
        gemm_mma<0><<<grid1, blk, SMEM_TOTAL>>>(pyt, pW1t, b1, nullptr, ph, nullptr,
                                                nullptr, nullptr, H_DIM, D_DIM);
        float* yo = (s == N_STEPS - 1) ? out : py;
        gemm_mma<2><<<grid2, blk, SMEM_TOTAL>>>(ph, pW2t, b2, yo, nullptr, pyr,
                                                ycur, pk1, D_DIM, H_DIM);
        ycur = py;
    }
}

// round 7
// speedup vs baseline: 8.4304x; 1.0385x over previous
#include <cuda_runtime.h>
#include <cuda_fp16.h>
#include <cstdint>
#include <cstddef>

#define M_BATCH 8192
#define D_DIM   512
#define H_DIM   2048
#define N_STEPS 10

// ---------------- scratch (device globals; no allocation allowed) ----------
__device__ float  g_y [M_BATCH * D_DIM];            // fp32 state
__device__ float  g_k1[M_BATCH * D_DIM];            // fp32 k1
__device__ __half g_yr[M_BATCH * D_DIM];            // fp16 copy of state (GEMM1 A)
__device__ __half g_yt[M_BATCH * D_DIM];            // fp16 y + dt*k1   (GEMM1 A)
__device__ __half g_h [M_BATCH * H_DIM];            // fp16 tanh hidden (GEMM2 A)
__device__ __half g_W1t[(size_t)H_DIM * D_DIM];     // W1^T fp16, [N=H, K=D]
__device__ __half g_W2t[(size_t)D_DIM * H_DIM];     // W2^T fp16, [N=D, K=H]

// ---------------- helpers ----------------------------------------------------
__device__ __forceinline__ uint32_t smem_u32(const void* p) {
    uint32_t a;
    asm("{ .reg .u64 t; cvta.to.shared.u64 t, %1; cvt.u32.u64 %0, t; }" : "=r"(a) : "l"(p));
    return a;
}
__device__ __forceinline__ float tanh_fast(float x) {       // MUFU.TANH
    float y;
    asm("tanh.approx.f32 %0, %1;" : "=f"(y) : "f"(x));
    return y;
}
__device__ __forceinline__ void mma_f16(float c[4], const uint32_t a[4], const uint32_t b[2]) {
    asm volatile(
        "mma.sync.aligned.m16n8k16.row.col.f32.f16.f16.f32 "
        "{%0,%1,%2,%3}, {%4,%5,%6,%7}, {%8,%9}, {%0,%1,%2,%3};"
        : "+f"(c[0]), "+f"(c[1]), "+f"(c[2]), "+f"(c[3])
        : "r"(a[0]), "r"(a[1]), "r"(a[2]), "r"(a[3]), "r"(b[0]), "r"(b[1]));
}
__device__ __forceinline__ void ldsm_x4(uint32_t r[4], uint32_t addr) {
    asm volatile("ldmatrix.sync.aligned.m8n8.x4.shared.b16 {%0,%1,%2,%3}, [%4];"
        : "=r"(r[0]), "=r"(r[1]), "=r"(r[2]), "=r"(r[3]) : "r"(addr));
}
#define CP_ASYNC16(dst, src) \
    asm volatile("cp.async.cg.shared.global [%0], [%1], 16;" :: "r"(dst), "l"(src))
#define CP_COMMIT() asm volatile("cp.async.commit_group;" ::: "memory")
#define CP_WAIT(n)  asm volatile("cp.async.wait_group %0;" :: "n"(n) : "memory")

// ---------------- GEMM config ------------------------------------------------
// CTA tile 128x128, BK=64 (fp16), 3 smem stages, 128 threads (4 warps: 2m x 2n,
// warp tile 64x64). Rows are 128B with XOR-16B-chunk swizzle: chunk' = chunk^(row&7).
constexpr int ROWB  = 128;                 // bytes per smem row
constexpr int ASZ   = 128 * ROWB;          // 16384 B per operand stage
constexpr int STGB  = 2 * ASZ;             // 32768 B per stage (A + B)
constexpr int NSTG  = 3;
constexpr int SMEM_TOTAL = NSTG * STGB;    // 98304 B -> 2 CTAs/SM

// MODE 0: Ch = fp16(tanh(acc + bias))
// MODE 1: Cf = acc + bias (k1, fp32);  C2h = fp16(yin + 0.1*k1)   (yt)
// MODE 2: yn = yin + 0.05*(k1in + (acc+bias)); Cf = yn (fp32); C2h = fp16(yn)
template<int MODE>
__global__ void __launch_bounds__(128, 2)
gemm_mma(const __half* __restrict__ A,     // [M, K] row-major fp16
         const __half* __restrict__ Bw,    // [N, K] row-major fp16 (K-major weights)
         const float* __restrict__ bias,
         float* __restrict__ Cf, __half* __restrict__ Ch, __half* __restrict__ C2h,
         const float* __restrict__ yin, const float* __restrict__ k1in,
         int N, int K)
{
    extern __shared__ char sm[];
    const uint32_t smb = smem_u32(sm);
    const int tid  = threadIdx.x;
    const int lane = tid & 31;
    const int wid  = tid >> 5;
    const int wm   = (wid & 1) * 64;      // warp m offset
    const int wn   = (wid >> 1) * 64;     // warp n offset
    const int g    = lane >> 2;           // 0..7 (epilogue row group)
    const int tig  = lane & 3;            // 0..3
    const int bm   = blockIdx.y * 128;
    const int bn   = blockIdx.x * 128;
    const int ktiles = K / 64;

    // ldmatrix lane decomposition
    const int e  = lane & 7;               // row-within-8 (== row&7 of target rows)
    const int m  = lane >> 3;              // matrix index 0..3
    const uint32_t rowA = (uint32_t)(wm + (m & 1) * 8 + e) * ROWB;   // + mt*16*ROWB
    const int      ca   = m >> 1;
    const uint32_t rowB = (uint32_t)(wn + (m >> 1) * 8 + e) * ROWB;  // + ntp*16*ROWB
    const int      cb   = m & 1;

    float acc[4][8][4];
    #pragma unroll
    for (int i = 0; i < 4; i++)
        #pragma unroll
        for (int j = 0; j < 8; j++)
            #pragma unroll
            for (int el = 0; el < 4; el++)
                acc[i][j][el] = 0.0f;

    // ---- async tile loader: 128 rows x 8 x 16B chunks per operand, 128 thr
    auto load_tile = [&](int kt) {
        const int s = kt % NSTG;
        const uint32_t sa = smb + s * STGB;
        const uint32_t sb = sa + ASZ;
        #pragma unroll
        for (int i = 0; i < 8; i++) {
            const int t   = tid + i * 128;       // 0..1023
            const int row = t >> 3;
            const int ch  = t & 7;
            const uint32_t off = (uint32_t)(row * ROWB + ((ch ^ (row & 7)) << 4));
            CP_ASYNC16(sa + off, A  + (size_t)(bm + row) * K + kt * 64 + ch * 8);
            CP_ASYNC16(sb + off, Bw + (size_t)(bn + row) * K + kt * 64 + ch * 8);
        }
    };

    // ---- prologue: 2 stages in flight ----
    #pragma unroll
    for (int kt = 0; kt < NSTG - 1; kt++) {
        if (kt < ktiles) load_tile(kt);
        CP_COMMIT();
    }

    // ---- mainloop ----
    for (int kt = 0; kt < ktiles; kt++) {
        if (kt + 1 < ktiles) { CP_WAIT(1); }
        else                 { CP_WAIT(0); }
        __syncthreads();

        if (kt + NSTG - 1 < ktiles) {
            load_tile(kt + NSTG - 1);
            CP_COMMIT();
        }

        const int s = kt % NSTG;
        const uint32_t sa = smb + s * STGB;
        const uint32_t sb = sa + ASZ;

        #pragma unroll
        for (int kq = 0; kq < 4; kq++) {          // 4 x k16
            uint32_t af[4][4], bf[8][2];
            // A fragments: 4 x ldmatrix.x4 (one per mt)
            #pragma unroll
            for (int mt = 0; mt < 4; mt++) {
                const uint32_t addr = sa + rowA + (uint32_t)(mt * 16) * ROWB
                                    + (uint32_t)(((2 * kq + ca) ^ e) << 4);
                ldsm_x4(af[mt], addr);
            }
            // B fragments: 4 x ldmatrix.x4 (each covers two n-tiles of 8)
            #pragma unroll
            for (int ntp = 0; ntp < 4; ntp++) {
                uint32_t r[4];
                const uint32_t addr = sb + rowB + (uint32_t)(ntp * 16) * ROWB
                                    + (uint32_t)(((2 * kq + cb) ^ e) << 4);
                ldsm_x4(r, addr);
                bf[2 * ntp + 0][0] = r[0];
                bf[2 * ntp + 0][1] = r[1];
                bf[2 * ntp + 1][0] = r[2];
                bf[2 * ntp + 1][1] = r[3];
            }
            #pragma unroll
            for (int mt = 0; mt < 4; mt++)
                #pragma unroll
                for (int nt = 0; nt < 8; nt++)
                    mma_f16(acc[mt][nt], af[mt], bf[nt]);
        }
    }

    // ---- fused epilogue ----
    #pragma unroll
    for (int mt = 0; mt < 4; mt++) {
        #pragma unroll
        for (int nt = 0; nt < 8; nt++) {
            const int col = bn + wn + nt * 8 + tig * 2;
            const float bv0 = __ldg(&bias[col]);
            const float bv1 = __ldg(&bias[col + 1]);
            #pragma unroll
            for (int half = 0; half < 2; half++) {
                const int row = bm + wm + mt * 16 + g + half * 8;
                const size_t idx = (size_t)row * N + col;
                const float v0 = acc[mt][nt][half * 2 + 0] + bv0;
                const float v1 = acc[mt][nt][half * 2 + 1] + bv1;
                if (MODE == 0) {
                    *reinterpret_cast<__half2*>(Ch + idx) =
                        __floats2half2_rn(tanh_fast(v0), tanh_fast(v1));
                } else if (MODE == 1) {
                    const float2 yv = *reinterpret_cast<const float2*>(yin + idx);
                    float2 o;  o.x = v0;  o.y = v1;                    // k1 fp32
                    *reinterpret_cast<float2*>(Cf + idx) = o;
                    *reinterpret_cast<__half2*>(C2h + idx) =
                        __floats2half2_rn(yv.x + 0.1f * v0, yv.y + 0.1f * v1);
                } else {
                    const float2 yv = *reinterpret_cast<const float2*>(yin + idx);
                    const float2 kv = *reinterpret_cast<const float2*>(k1in + idx);
                    float2 o;
                    o.x = yv.x + 0.05f * (kv.x + v0);                  // y_next fp32
                    o.y = yv.y + 0.05f * (kv.y + v1);
                    *reinterpret_cast<float2*>(Cf + idx) = o;
                    *reinterpret_cast<__half2*>(C2h + idx) = __floats2half2_rn(o.x, o.y);
                }
            }
        }
    }
}

// ---------------- prep kernels ------------------------------------------------
__global__ void transpose_half(const float* __restrict__ in, __half* __restrict__ out,
                               int R, int C)
{
    __shared__ float t[32][33];
    const int bx = blockIdx.x * 32, by = blockIdx.y * 32;
    #pragma unroll
    for (int j = 0; j < 32; j += 8)
        t[threadIdx.y + j][threadIdx.x] = in[(size_t)(by + threadIdx.y + j) * C + bx + threadIdx.x];
    __syncthreads();
    #pragma unroll
    for (int j = 0; j < 32; j += 8)
        out[(size_t)(bx + threadIdx.y + j) * R + by + threadIdx.x] =
            __float2half_rn(t[threadIdx.x][threadIdx.y + j]);
}

__global__ void half_copy(const float* __restrict__ in, __half* __restrict__ out, int n4)
{
    const int i = blockIdx.x * blockDim.x + threadIdx.x;
    if (i < n4) {
        const float4 v = reinterpret_cast<const float4*>(in)[i];
        __half2 h0 = __floats2half2_rn(v.x, v.y);
        __half2 h1 = __floats2half2_rn(v.z, v.w);
        reinterpret_cast<__half2*>(out)[i * 2 + 0] = h0;
        reinterpret_cast<__half2*>(out)[i * 2 + 1] = h1;
    }
}

// ---------------- launch --------------------------------------------------------
extern "C" void kernel_launch(void* const* d_in, const int* in_sizes, int n_in,
                              void* d_out, int out_size)
{
    const float* y0 = (const float*)d_in[0];
    const float* W1 = (const float*)d_in[1];
    const float* b1 = (const float*)d_in[2];
    const float* W2 = (const float*)d_in[3];
    const float* b2 = (const float*)d_in[4];
    float* out = (float*)d_out;

    float *py, *pk1;
    __half *pyr, *pyt, *ph, *pW1t, *pW2t;
    cudaGetSymbolAddress((void**)&py,   g_y);
    cudaGetSymbolAddress((void**)&pk1,  g_k1);
    cudaGetSymbolAddress((void**)&pyr,  g_yr);
    cudaGetSymbolAddress((void**)&pyt,  g_yt);
    cudaGetSymbolAddress((void**)&ph,   g_h);
    cudaGetSymbolAddress((void**)&pW1t, g_W1t);
    cudaGetSymbolAddress((void**)&pW2t, g_W2t);

    cudaFuncSetAttribute(gemm_mma<0>, cudaFuncAttributeMaxDynamicSharedMemorySize, SMEM_TOTAL);
    cudaFuncSetAttribute(gemm_mma<1>, cudaFuncAttributeMaxDynamicSharedMemorySize, SMEM_TOTAL);
    cudaFuncSetAttribute(gemm_mma<2>, cudaFuncAttributeMaxDynamicSharedMemorySize, SMEM_TOTAL);

    // weights -> K-major fp16; y0 -> fp16 copy
    transpose_half<<<dim3(H_DIM / 32, D_DIM / 32), dim3(32, 8)>>>(W1, pW1t, D_DIM, H_DIM);
    transpose_half<<<dim3(D_DIM / 32, H_DIM / 32), dim3(32, 8)>>>(W2, pW2t, H_DIM, D_DIM);
    {
        const int n4 = M_BATCH * D_DIM / 4;
        half_copy<<<(n4 + 255) / 256, 256>>>(y0, pyr, n4);
    }

    const dim3 blk(128);
    const dim3 grid1(H_DIM / 128, M_BATCH / 128);   // 16 x 64
    const dim3 grid2(D_DIM / 128, M_BATCH / 128);   //  4 x 64

    const float* ycur = y0;                          // fp32 state input
    for (int s = 0; s < N_STEPS; s++) {
        // k1 pass: h = tanh(yr@W1t + b1); k1 = h@W2t + b2; yt = fp16(y + dt*k1)
        gemm_mma<0><<<grid1, blk, SMEM_TOTAL>>>(pyr, pW1t, b1, nullptr, ph, nullptr,
                                                nullptr, nullptr, H_DIM, D_DIM);
        gemm_mma<1><<<grid2, blk, SMEM_TOTAL>>>(ph, pW2t, b2, pk1, nullptr, pyt,
                                                ycur, nullptr, D_DIM, H_DIM);
        // k2 pass: h = tanh(yt@W1t + b1); y = y + 0.05*(k1 + k2); yr = fp16(y)
        gemm_mma<0><<<grid1, blk, SMEM_TOTAL>>>(pyt, pW1t, b1, nullptr, ph, nullptr,
                                                nullptr, nullptr, H_DIM, D_DIM);
        float* yo = (s == N_STEPS - 1) ? out : py;
        gemm_mma<2><<<grid2, blk, SMEM_TOTAL>>>(ph, pW2t, b2, yo, nullptr, pyr,
                                                ycur, pk1, D_DIM, H_DIM);
        ycur = py;
    }
}

// round 8
// speedup vs baseline: 8.4414x; 1.0013x over previous
#include <cuda_runtime.h>
#include <cuda_fp16.h>
#include <cstdint>
#include <cstddef>

#define M_BATCH 8192
#define D_DIM   512
#define H_DIM   2048
#define N_STEPS 10

// ---------------- scratch (device globals; no allocation allowed) ----------
__device__ float  g_y [M_BATCH * D_DIM];            // fp32 state
__device__ float  g_k1[M_BATCH * D_DIM];            // fp32 k1
__device__ __half g_yr[M_BATCH * D_DIM];            // fp16 copy of state (G1 A)
__device__ __half g_yt[M_BATCH * D_DIM];            // fp16 y + dt*k1   (G1 A)
__device__ __half g_h [M_BATCH * H_DIM];            // fp16 tanh hidden (G2 A)
__device__ __half g_W1t[(size_t)H_DIM * D_DIM];     // W1^T fp16, [N=H, K=D]
__device__ __half g_W2t[(size_t)D_DIM * H_DIM];     // W2^T fp16, [N=D, K=H]
__device__ int    g_cnt[40 * 64];                   // per-(phase, bm-row) completion counters

// ---------------- work-list constants ----------------------------------------
constexpr int TILES_G1   = 1024;   // 64 x 16 tiles of 128x128 (out 8192x2048)
constexpr int TILES_G2   = 256;    // 64 x  4 tiles of 128x128 (out 8192x512)
constexpr int TILES_STEP = 2 * TILES_G1 + 2 * TILES_G2;   // 2560
constexpr int TILES_TOT  = N_STEPS * TILES_STEP;          // 25600

// ---------------- helpers ----------------------------------------------------
__device__ __forceinline__ uint32_t smem_u32(const void* p) {
    uint32_t a;
    asm("{ .reg .u64 t; cvta.to.shared.u64 t, %1; cvt.u32.u64 %0, t; }" : "=r"(a) : "l"(p));
    return a;
}
__device__ __forceinline__ float tanh_fast(float x) {       // MUFU.TANH
    float y;
    asm("tanh.approx.f32 %0, %1;" : "=f"(y) : "f"(x));
    return y;
}
__device__ __forceinline__ void mma_f16(float c[4], const uint32_t a[4], const uint32_t b[2]) {
    asm volatile(
        "mma.sync.aligned.m16n8k16.row.col.f32.f16.f16.f32 "
        "{%0,%1,%2,%3}, {%4,%5,%6,%7}, {%8,%9}, {%0,%1,%2,%3};"
        : "+f"(c[0]), "+f"(c[1]), "+f"(c[2]), "+f"(c[3])
        : "r"(a[0]), "r"(a[1]), "r"(a[2]), "r"(a[3]), "r"(b[0]), "r"(b[1]));
}
__device__ __forceinline__ void ldsm_x4(uint32_t r[4], uint32_t addr) {
    asm volatile("ldmatrix.sync.aligned.m8n8.x4.shared.b16 {%0,%1,%2,%3}, [%4];"
        : "=r"(r[0]), "=r"(r[1]), "=r"(r[2]), "=r"(r[3]) : "r"(addr));
}
__device__ __forceinline__ int ld_acquire(const int* p) {
    int v;
    asm volatile("ld.acquire.gpu.global.b32 %0, [%1];" : "=r"(v) : "l"(p) : "memory");
    return v;
}
#define CP_ASYNC16(dst, src) \
    asm volatile("cp.async.cg.shared.global [%0], [%1], 16;" :: "r"(dst), "l"(src))
#define CP_COMMIT() asm volatile("cp.async.commit_group;" ::: "memory")
#define CP_WAIT(n)  asm volatile("cp.async.wait_group %0;" :: "n"(n) : "memory")

// ---------------- GEMM config ------------------------------------------------
// CTA tile 128x128, BK=64 (fp16), 3 smem stages, 128 threads (4 warps 2m x 2n,
// warp tile 64x64). Rows 128B with XOR-16B-chunk swizzle: chunk' = chunk^(row&7).
constexpr int ROWB  = 128;
constexpr int ASZ   = 128 * ROWB;          // 16384 B per operand stage
constexpr int STGB  = 2 * ASZ;             // 32768 B per stage (A + B)
constexpr int NSTG  = 3;
constexpr int SMEM_TOTAL = NSTG * STGB;    // 98304 B -> 2 CTAs/SM

// One 128x128 output tile of C = A @ Bw^T (+ fused epilogue by mode).
// mode 0: Ch = fp16(tanh(acc + bias))
// mode 1: Cf = acc + bias (k1, fp32);  C2h = fp16(yin + 0.1*k1)   (yt)
// mode 2: yn = yin + 0.05*(k1in + (acc+bias)); Cf = yn; C2h = fp16(yn)
__device__ __forceinline__ void do_tile(
    int mode, int bm, int bn,
    const __half* __restrict__ A, const __half* __restrict__ Bw,
    const float* __restrict__ bias,
    float* __restrict__ Cf, __half* __restrict__ Ch, __half* __restrict__ C2h,
    const float* __restrict__ yin, const float* __restrict__ k1in,
    int N, int K, uint32_t smb)
{
    const int tid  = threadIdx.x;
    const int lane = tid & 31;
    const int wid  = tid >> 5;
    const int wm   = (wid & 1) * 64;
    const int wn   = (wid >> 1) * 64;
    const int g    = lane >> 2;
    const int tig  = lane & 3;
    const int ktiles = K / 64;

    const int e = lane & 7;
    const int m = lane >> 3;
    const uint32_t rowA = (uint32_t)(wm + (m & 1) * 8 + e) * ROWB;
    const int      ca   = m >> 1;
    const uint32_t rowB = (uint32_t)(wn + (m >> 1) * 8 + e) * ROWB;
    const int      cb   = m & 1;

    float acc[4][8][4];
    #pragma unroll
    for (int i = 0; i < 4; i++)
        #pragma unroll
        for (int j = 0; j < 8; j++)
            #pragma unroll
            for (int el = 0; el < 4; el++)
                acc[i][j][el] = 0.0f;

    auto load_tile = [&](int kt) {
        const int s = kt % NSTG;
        const uint32_t sa = smb + s * STGB;
        const uint32_t sb = sa + ASZ;
        #pragma unroll
        for (int i = 0; i < 8; i++) {
            const int t   = tid + i * 128;
            const int row = t >> 3;
            const int ch  = t & 7;
            const uint32_t off = (uint32_t)(row * ROWB + ((ch ^ (row & 7)) << 4));
            CP_ASYNC16(sa + off, A  + (size_t)(bm + row) * K + kt * 64 + ch * 8);
            CP_ASYNC16(sb + off, Bw + (size_t)(bn + row) * K + kt * 64 + ch * 8);
        }
    };

    #pragma unroll
    for (int kt = 0; kt < NSTG - 1; kt++) {
        if (kt < ktiles) load_tile(kt);
        CP_COMMIT();
    }

    for (int kt = 0; kt < ktiles; kt++) {
        if (kt + 1 < ktiles) { CP_WAIT(1); }
        else                 { CP_WAIT(0); }
        __syncthreads();

        if (kt + NSTG - 1 < ktiles) {
            load_tile(kt + NSTG - 1);
            CP_COMMIT();
        }

        const int s = kt % NSTG;
        const uint32_t sa = smb + s * STGB;
        const uint32_t sb = sa + ASZ;

        #pragma unroll
        for (int kq = 0; kq < 4; kq++) {
            uint32_t af[4][4], bf[8][2];
            #pragma unroll
            for (int mt = 0; mt < 4; mt++) {
                const uint32_t addr = sa + rowA + (uint32_t)(mt * 16) * ROWB
                                    + (uint32_t)(((2 * kq + ca) ^ e) << 4);
                ldsm_x4(af[mt], addr);
            }
            #pragma unroll
            for (int ntp = 0; ntp < 4; ntp++) {
                uint32_t r[4];
                const uint32_t addr = sb + rowB + (uint32_t)(ntp * 16) * ROWB
                                    + (uint32_t)(((2 * kq + cb) ^ e) << 4);
                ldsm_x4(r, addr);
                bf[2 * ntp + 0][0] = r[0];
                bf[2 * ntp + 0][1] = r[1];
                bf[2 * ntp + 1][0] = r[2];
                bf[2 * ntp + 1][1] = r[3];
            }
            #pragma unroll
            for (int mt = 0; mt < 4; mt++)
                #pragma unroll
                for (int nt = 0; nt < 8; nt++)
                    mma_f16(acc[mt][nt], af[mt], bf[nt]);
        }
    }

    // fused epilogue
    #pragma unroll
    for (int mt = 0; mt < 4; mt++) {
        #pragma unroll
        for (int nt = 0; nt < 8; nt++) {
            const int col = bn + wn + nt * 8 + tig * 2;
            const float bv0 = __ldg(&bias[col]);
            const float bv1 = __ldg(&bias[col + 1]);
            #pragma unroll
            for (int half = 0; half < 2; half++) {
                const int row = bm + wm + mt * 16 + g + half * 8;
                const size_t idx = (size_t)row * N + col;
                const float v0 = acc[mt][nt][half * 2 + 0] + bv0;
                const float v1 = acc[mt][nt][half * 2 + 1] + bv1;
                if (mode == 0) {
                    *reinterpret_cast<__half2*>(Ch + idx) =
                        __floats2half2_rn(tanh_fast(v0), tanh_fast(v1));
                } else if (mode == 1) {
                    const float2 yv = *reinterpret_cast<const float2*>(yin + idx);
                    float2 o;  o.x = v0;  o.y = v1;
                    *reinterpret_cast<float2*>(Cf + idx) = o;
                    *reinterpret_cast<__half2*>(C2h + idx) =
                        __floats2half2_rn(yv.x + 0.1f * v0, yv.y + 0.1f * v1);
                } else {
                    const float2 yv = *reinterpret_cast<const float2*>(yin + idx);
                    const float2 kv = *reinterpret_cast<const float2*>(k1in + idx);
                    float2 o;
                    o.x = yv.x + 0.05f * (kv.x + v0);
                    o.y = yv.y + 0.05f * (kv.y + v1);
                    *reinterpret_cast<float2*>(Cf + idx) = o;
                    *reinterpret_cast<__half2*>(C2h + idx) = __floats2half2_rn(o.x, o.y);
                }
            }
        }
    }
}

// ---------------- persistent scheduler kernel ---------------------------------
__global__ void __launch_bounds__(128, 2)
heun_persistent(const float* __restrict__ y0, const float* __restrict__ b1,
                const float* __restrict__ b2, float* __restrict__ out, int nCTA)
{
    extern __shared__ char sm[];
    const uint32_t smb = smem_u32(sm);
    const int tid = threadIdx.x;

    for (int item = blockIdx.x; item < TILES_TOT; item += nCTA) {
        // ---- decode work item -> (step, q, tile) ----
        const int step = item / TILES_STEP;
        const int r    = item - step * TILES_STEP;
        int q, t;
        if      (r < TILES_G1)                 { q = 0; t = r; }
        else if (r < TILES_G1 + TILES_G2)      { q = 1; t = r - TILES_G1; }
        else if (r < 2 * TILES_G1 + TILES_G2)  { q = 2; t = r - TILES_G1 - TILES_G2; }
        else                                   { q = 3; t = r - 2 * TILES_G1 - TILES_G2; }
        const int phase = step * 4 + q;
        const bool isG1 = (q & 1) == 0;
        const int bmIdx = isG1 ? (t >> 4) : (t >> 2);
        const int bn    = (isG1 ? (t & 15) : (t & 3)) * 128;
        const int bm    = bmIdx * 128;

        // ---- wait for producer phase (per bm row) ----
        if (phase > 0) {
            const int target = isG1 ? 4 : 16;     // prev phase tiles per bm row
            const int* cp = &g_cnt[(phase - 1) * 64 + bmIdx];
            if (tid == 0) {
                while (ld_acquire(cp) < target) __nanosleep(64);
            }
            __syncthreads();
        }

        // ---- pointers per phase ----
        const float* ycur = (step == 0) ? y0 : g_y;
        if (isG1) {
            const __half* A = (q == 0) ? g_yr : g_yt;
            do_tile(0, bm, bn, A, g_W1t, b1,
                    nullptr, g_h, nullptr, nullptr, nullptr,
                    H_DIM, D_DIM, smb);
        } else if (q == 1) {
            do_tile(1, bm, bn, g_h, g_W2t, b2,
                    g_k1, nullptr, g_yt, ycur, nullptr,
                    D_DIM, H_DIM, smb);
        } else {
            float* yo = (step == N_STEPS - 1) ? out : g_y;
            do_tile(2, bm, bn, g_h, g_W2t, b2,
                    yo, nullptr, g_yr, ycur, g_k1,
                    D_DIM, H_DIM, smb);
        }

        // ---- publish completion ----
        __syncthreads();
        if (tid == 0) {
            __threadfence();
            atomicAdd(&g_cnt[phase * 64 + bmIdx], 1);
        }
    }
}

// ---------------- prep kernels ------------------------------------------------
__global__ void zero_cnt()
{
    const int i = blockIdx.x * blockDim.x + threadIdx.x;
    if (i < 40 * 64) g_cnt[i] = 0;
}

__global__ void transpose_half(const float* __restrict__ in, __half* __restrict__ out,
                               int R, int C)
{
    __shared__ float t[32][33];
    const int bx = blockIdx.x * 32, by = blockIdx.y * 32;
    #pragma unroll
    for (int j = 0; j < 32; j += 8)
        t[threadIdx.y + j][threadIdx.x] = in[(size_t)(by + threadIdx.y + j) * C + bx + threadIdx.x];
    __syncthreads();
    #pragma unroll
    for (int j = 0; j < 32; j += 8)
        out[(size_t)(bx + threadIdx.y + j) * R + by + threadIdx.x] =
            __float2half_rn(t[threadIdx.x][threadIdx.y + j]);
}

__global__ void half_copy(const float* __restrict__ in, __half* __restrict__ out, int n4)
{
    const int i = blockIdx.x * blockDim.x + threadIdx.x;
    if (i < n4) {
        const float4 v = reinterpret_cast<const float4*>(in)[i];
        reinterpret_cast<__half2*>(out)[i * 2 + 0] = __floats2half2_rn(v.x, v.y);
        reinterpret_cast<__half2*>(out)[i * 2 + 1] = __floats2half2_rn(v.z, v.w);
    }
}

// ---------------- launch --------------------------------------------------------
extern "C" void kernel_launch(void* const* d_in, const int* in_sizes, int n_in,
                              void* d_out, int out_size)
{
    const float* y0 = (const float*)d_in[0];
    const float* W1 = (const float*)d_in[1];
    const float* b1 = (const float*)d_in[2];
    const float* W2 = (const float*)d_in[3];
    const float* b2 = (const float*)d_in[4];
    float* out = (float*)d_out;

    __half *pyr, *pW1t, *pW2t;
    cudaGetSymbolAddress((void**)&pyr,  g_yr);
    cudaGetSymbolAddress((void**)&pW1t, g_W1t);
    cudaGetSymbolAddress((void**)&pW2t, g_W2t);

    cudaFuncSetAttribute(heun_persistent,
                         cudaFuncAttributeMaxDynamicSharedMemorySize, SMEM_TOTAL);

    // grid: all CTAs must be co-resident (spin-wait safety)
    int dev = 0, sms = 0, occ = 0;
    cudaGetDevice(&dev);
    cudaDeviceGetAttribute(&sms, cudaDevAttrMultiProcessorCount, dev);
    cudaOccupancyMaxActiveBlocksPerMultiprocessor(&occ, heun_persistent, 128, SMEM_TOTAL);
    if (occ < 1) occ = 1;
    if (occ > 2) occ = 2;
    const int nCTA = sms * occ;

    // prep: counters, weights -> K-major fp16, y0 -> fp16 copy
    zero_cnt<<<10, 256>>>();
    transpose_half<<<dim3(H_DIM / 32, D_DIM / 32), dim3(32, 8)>>>(W1, pW1t, D_DIM, H_DIM);
    transpose_half<<<dim3(D_DIM / 32, H_DIM / 32), dim3(32, 8)>>>(W2, pW2t, H_DIM, D_DIM);
    {
        const int n4 = M_BATCH * D_DIM / 4;
        half_copy<<<(n4 + 255) / 256, 256>>>(y0, pyr, n4);
    }

    heun_persistent<<<nCTA, 128, SMEM_TOTAL>>>(y0, b1, b2, out, nCTA);
}